// round 2
// baseline (speedup 1.0000x reference)
#include <cuda_runtime.h>
#include <cuda_bf16.h>

#define B 256
#define S 512
#define E 100
#define H 64
#define G 256   // 4*H gates
#define SB (S*B)

// Scratch: input projections for both directions, layout ((dir*S + t)*B + b)*G + g
__device__ float g_xproj[2L * S * B * G];   // 268 MB
__device__ float g_hfin[2 * B * H];         // final hidden states

__device__ __forceinline__ float sigmf(float x) {
    return 1.0f / (1.0f + __expf(-x));
}

// ---------------------------------------------------------------------------
// Kernel 1: fused embedding gather + input projection GEMM (+bias)
//   C[row, j] = sum_k emb[x[b,t], k] * W_ih[j, k] + b_ih[j] + b_hh[j]
//   row = t*B + b, M = 131072, N = 256, K = 100, two directions (blockIdx.z)
// Tile: 64x64, 256 threads, 4x4 microtile, K chunks of 50.
// ---------------------------------------------------------------------------
#define TM 64
#define TN 64
#define TK 50
#define PAD 68   // smem row stride (floats): 16B-aligned, conflict-light

__global__ __launch_bounds__(256, 2)
void embed_proj_gemm(const int* __restrict__ x,
                     const float* __restrict__ emb,
                     const float* __restrict__ Wih_f,
                     const float* __restrict__ bih_f,
                     const float* __restrict__ bhh_f,
                     const float* __restrict__ Wih_b,
                     const float* __restrict__ bih_b,
                     const float* __restrict__ bhh_b)
{
    const int tid = threadIdx.x;
    const int tx = tid & 15;        // 0..15 -> N
    const int ty = tid >> 4;        // 0..15 -> M
    const int rb = blockIdx.x * TM; // row base
    const int cb = blockIdx.y * TN; // col base
    const int dir = blockIdx.z;

    const float* __restrict__ Wih = dir ? Wih_b : Wih_f;
    const float* __restrict__ bih = dir ? bih_b : bih_f;
    const float* __restrict__ bhh = dir ? bhh_b : bhh_f;

    __shared__ float As[TK][PAD];
    __shared__ float Bs[TK][PAD];
    __shared__ int   toks[TM];

    if (tid < TM) {
        int gr = rb + tid;              // global row = t*B + b
        int t = gr >> 8;                // / 256
        int b = gr & 255;
        toks[tid] = x[b * S + t];
    }
    __syncthreads();

    float acc[4][4];
#pragma unroll
    for (int i = 0; i < 4; i++)
#pragma unroll
        for (int j = 0; j < 4; j++) acc[i][j] = 0.0f;

    for (int kc = 0; kc < E; kc += TK) {
        // Stage A: As[k][r] = emb[tok[r]*E + kc + k]
        for (int idx = tid; idx < TM * TK; idx += 256) {
            int r = idx / TK;
            int k = idx - r * TK;
            As[k][r] = emb[(long)toks[r] * E + kc + k];
        }
        // Stage B: Bs[k][j] = Wih[(cb+j)*E + kc + k]
        for (int idx = tid; idx < TN * TK; idx += 256) {
            int j = idx / TK;
            int k = idx - j * TK;
            Bs[k][j] = Wih[(cb + j) * E + kc + k];
        }
        __syncthreads();

#pragma unroll
        for (int k = 0; k < TK; k++) {
            float4 av = *(const float4*)&As[k][ty * 4];
            float4 bv = *(const float4*)&Bs[k][tx * 4];
            float a[4] = {av.x, av.y, av.z, av.w};
            float b4[4] = {bv.x, bv.y, bv.z, bv.w};
#pragma unroll
            for (int i = 0; i < 4; i++)
#pragma unroll
                for (int j = 0; j < 4; j++)
                    acc[i][j] = fmaf(a[i], b4[j], acc[i][j]);
        }
        __syncthreads();
    }

    // bias (b_ih + b_hh) and store
    int cg = cb + tx * 4;
    float4 bi = *(const float4*)&bih[cg];
    float4 bh = *(const float4*)&bhh[cg];
    float4 bias = make_float4(bi.x + bh.x, bi.y + bh.y, bi.z + bh.z, bi.w + bh.w);

    float* out = g_xproj + (size_t)dir * S * B * G;
#pragma unroll
    for (int i = 0; i < 4; i++) {
        int row = rb + ty * 4 + i;
        float4 o;
        o.x = acc[i][0] + bias.x;
        o.y = acc[i][1] + bias.y;
        o.z = acc[i][2] + bias.z;
        o.w = acc[i][3] + bias.w;
        *(float4*)&out[(size_t)row * G + cg] = o;
    }
}

// ---------------------------------------------------------------------------
// Kernel 2: LSTM recurrence. One block per (batch row, direction).
// Thread j (0..255) owns gate j: keeps W_hh[j][0..63] in registers.
// h lives in shared memory (broadcast reads). Threads 0..63 update c,h.
// ---------------------------------------------------------------------------
__global__ __launch_bounds__(256, 2)
void lstm_recurrent(const float* __restrict__ Whh_f,
                    const float* __restrict__ Whh_b)
{
    const int b = blockIdx.x;
    const int dir = blockIdx.y;
    const int j = threadIdx.x;

    const float* __restrict__ W = dir ? Whh_b : Whh_f;

    float w[H];
#pragma unroll
    for (int m = 0; m < 16; m++) {
        float4 v = *(const float4*)&W[j * H + m * 4];
        w[4 * m + 0] = v.x; w[4 * m + 1] = v.y;
        w[4 * m + 2] = v.z; w[4 * m + 3] = v.w;
    }

    __shared__ float h_sh[H];
    __shared__ float gates[G];

    if (j < H) h_sh[j] = 0.0f;
    float c = 0.0f;

    const float* __restrict__ xp_base =
        g_xproj + (size_t)dir * S * B * G + (size_t)b * G + j;
    // xp index per step: xp_base[t * B * G]

    __syncthreads();

    int t = dir ? (S - 1) : 0;
    const int dt = dir ? -1 : 1;

    float xp = xp_base[(size_t)t * B * G];

    for (int s = 0; s < S; s++) {
        int t2 = t + dt;
        // prefetch next step's input projection (hide DRAM latency)
        float xp_next = (s < S - 1) ? xp_base[(size_t)t2 * B * G] : 0.0f;

        float acc = xp;
        const float4* h4 = (const float4*)h_sh;
#pragma unroll
        for (int m = 0; m < 16; m++) {
            float4 hv = h4[m];
            acc = fmaf(hv.x, w[4 * m + 0], acc);
            acc = fmaf(hv.y, w[4 * m + 1], acc);
            acc = fmaf(hv.z, w[4 * m + 2], acc);
            acc = fmaf(hv.w, w[4 * m + 3], acc);
        }
        gates[j] = acc;
        __syncthreads();

        if (j < H) {
            float gi = gates[j];
            float gf = gates[H + j];
            float gg = gates[2 * H + j];
            float go = gates[3 * H + j];
            c = sigmf(gf) * c + sigmf(gi) * tanhf(gg);
            h_sh[j] = sigmf(go) * tanhf(c);
        }
        __syncthreads();

        xp = xp_next;
        t = t2;
    }

    if (j < H) g_hfin[(dir * B + b) * H + j] = h_sh[j];
}

// ---------------------------------------------------------------------------
// Kernel 3: final FC + sigmoid. out[b] = sigm(h_cat[b] . fc_w + fc_b)
// ---------------------------------------------------------------------------
__global__ void final_fc(const float* __restrict__ fcw,
                         const float* __restrict__ fcb,
                         float* __restrict__ out)
{
    int b = threadIdx.x;
    if (b >= B) return;
    float acc = fcb[0];
    const float* hf = g_hfin + b * H;            // forward dir
    const float* hb = g_hfin + B * H + b * H;    // backward dir
#pragma unroll
    for (int u = 0; u < H; u++) {
        acc = fmaf(hf[u], fcw[u], acc);
        acc = fmaf(hb[u], fcw[H + u], acc);
    }
    out[b] = sigmf(acc);
}

// ---------------------------------------------------------------------------
extern "C" void kernel_launch(void* const* d_in, const int* in_sizes, int n_in,
                              void* d_out, int out_size)
{
    const int*   x     = (const int*)  d_in[0];
    const float* emb   = (const float*)d_in[1];
    const float* Wih_f = (const float*)d_in[2];
    const float* Whh_f = (const float*)d_in[3];
    const float* bih_f = (const float*)d_in[4];
    const float* bhh_f = (const float*)d_in[5];
    const float* Wih_b = (const float*)d_in[6];
    const float* Whh_b = (const float*)d_in[7];
    const float* bih_b = (const float*)d_in[8];
    const float* bhh_b = (const float*)d_in[9];
    const float* fcw   = (const float*)d_in[10];
    const float* fcb   = (const float*)d_in[11];
    float* out = (float*)d_out;

    // Phase 1: input projections for both directions
    dim3 g1(SB / TM, G / TN, 2);   // 2048 x 4 x 2
    embed_proj_gemm<<<g1, 256>>>(x, emb, Wih_f, bih_f, bhh_f, Wih_b, bih_b, bhh_b);

    // Phase 2: recurrence, one block per (batch, direction)
    dim3 g2(B, 2);
    lstm_recurrent<<<g2, 256>>>(Whh_f, Whh_b);

    // Phase 3: output head
    final_fc<<<1, 256>>>(fcw, fcb, out);
}

// round 3
// speedup vs baseline: 2.4045x; 2.4045x over previous
#include <cuda_runtime.h>
#include <cuda_bf16.h>

#define Bz 256
#define Sz 512
#define Ez 100
#define Hz 64
#define Gz 256      // 4*H
#define Vz 50000
#define VP 50048    // padded vocab rows (782*64)
#define NC 512      // 2 dirs * 256 gates

// Precomputed per-vocab input projections (+bias), layout [VP][NC]
__device__ float g_table[(size_t)VP * NC];   // ~102.5 MB, fits mostly in L2
__device__ float g_hfin[2 * Bz * Hz];

// ---- f32x2 packed-math helpers (FFMA2 only reachable via PTX) ----
#define FMA2(acc, a, b) \
    asm("fma.rn.f32x2 %0, %1, %2, %0;" : "+l"(acc) : "l"(a), "l"(b))
#define DUP2(d, a) \
    asm("mov.b64 %0, {%1, %1};" : "=l"(d) : "f"(a))
#define PACK2(d, a, b) \
    asm("mov.b64 %0, {%1, %2};" : "=l"(d) : "f"(a), "f"(b))
#define UNPACK2(a, b, d) \
    asm("mov.b64 {%0, %1}, %2;" : "=f"(a), "=f"(b) : "l"(d))

__device__ __forceinline__ float sigmf(float x) {
    return __fdividef(1.0f, 1.0f + __expf(-x));
}
__device__ __forceinline__ float tanhp(float x) {
    // tanh(x) = 2*sigmoid(2x) - 1, error ~1e-6 with EX2/RCP MUFU path
    return fmaf(2.0f, sigmf(2.0f * x), -1.0f);
}

// ---------------------------------------------------------------------------
// Kernel 1: vocab-table GEMM.
//   table[v, dir*256+g] = sum_k emb[v,k] * W_ih[g,k] + (b_ih[g]+b_hh[g])
//   M=50048(pad), N=512, K=100.  Tile 64x64, 256 thr, 4x4 microtile, f32x2 on N.
// ---------------------------------------------------------------------------
#define TKc 50
#define LDA 68   // smem row stride (floats), 16B-aligned, conflict-free staging

__global__ __launch_bounds__(256)
void vocab_gemm(const float* __restrict__ emb,
                const float* __restrict__ Wih_f,
                const float* __restrict__ bih_f,
                const float* __restrict__ bhh_f,
                const float* __restrict__ Wih_b,
                const float* __restrict__ bih_b,
                const float* __restrict__ bhh_b)
{
    const int tid = threadIdx.x;
    const int tx = tid & 15;          // N microtile (4 cols = 2 f32x2)
    const int ty = tid >> 4;          // M microtile (4 rows)
    const int rb = blockIdx.x * 64;   // vocab row base
    const int cb = blockIdx.y * 64;   // column base (0..448)
    const int dir = cb >> 8;
    const int gb  = cb & 255;

    const float* __restrict__ W  = dir ? Wih_b : Wih_f;
    const float* __restrict__ bi = dir ? bih_b : bih_f;
    const float* __restrict__ bh = dir ? bhh_b : bhh_f;

    __shared__ __align__(16) float As[TKc * LDA];
    __shared__ __align__(16) float Bs[TKc * LDA];
    __shared__ float bias_s[64];

    if (tid < 64) bias_s[tid] = bi[gb + tid] + bh[gb + tid];

    unsigned long long acc[4][2];
#pragma unroll
    for (int i = 0; i < 4; i++) { acc[i][0] = 0ull; acc[i][1] = 0ull; }

    const float2* __restrict__ emb2 = (const float2*)emb;
    const float2* __restrict__ W2   = (const float2*)W;

    for (int kc = 0; kc < Ez; kc += TKc) {
        if (kc) __syncthreads();   // protect smem reuse across chunks
        // Stage: 64 rows x 25 float2 per buffer; conflict-free STS pattern.
        for (int p = tid; p < 64 * 25; p += 256) {
            int q = p % 25;        // float2 index within chunk
            int m = p / 25;        // row within tile
            int row = rb + m; if (row >= Vz) row = Vz - 1;
            float2 va = emb2[(size_t)row * 50 + (kc >> 1) + q];
            As[(2 * q)     * LDA + m] = va.x;
            As[(2 * q + 1) * LDA + m] = va.y;
            float2 vb = W2[(size_t)(gb + m) * 50 + (kc >> 1) + q];
            Bs[(2 * q)     * LDA + m] = vb.x;
            Bs[(2 * q + 1) * LDA + m] = vb.y;
        }
        __syncthreads();

#pragma unroll 10
        for (int k = 0; k < TKc; k++) {
            float4 a4 = *(const float4*)(As + k * LDA + ty * 4);
            ulonglong2 b2 = *(const ulonglong2*)(Bs + k * LDA + tx * 4);
            unsigned long long ad0, ad1, ad2, ad3;
            DUP2(ad0, a4.x); DUP2(ad1, a4.y);
            DUP2(ad2, a4.z); DUP2(ad3, a4.w);
            FMA2(acc[0][0], ad0, b2.x); FMA2(acc[0][1], ad0, b2.y);
            FMA2(acc[1][0], ad1, b2.x); FMA2(acc[1][1], ad1, b2.y);
            FMA2(acc[2][0], ad2, b2.x); FMA2(acc[2][1], ad2, b2.y);
            FMA2(acc[3][0], ad3, b2.x); FMA2(acc[3][1], ad3, b2.y);
        }
    }

    float4 bb = *(const float4*)(bias_s + tx * 4);
#pragma unroll
    for (int i = 0; i < 4; i++) {
        float c0, c1, c2, c3;
        UNPACK2(c0, c1, acc[i][0]);
        UNPACK2(c2, c3, acc[i][1]);
        float4 o = make_float4(c0 + bb.x, c1 + bb.y, c2 + bb.z, c3 + bb.w);
        int row = rb + ty * 4 + i;                   // < VP, always in bounds
        *(float4*)&g_table[(size_t)row * NC + cb + tx * 4] = o;
    }
}

// ---------------------------------------------------------------------------
// Kernel 2: LSTM recurrence, 4 batch rows per block -> 128 blocks = 1 wave.
// Thread j (0..255): matvec for gate j over 4 rows (4 independent f32x2 chains);
// update phase: thread j owns cell (r=j>>6, e=j&63).
// xp gathered directly from g_table (L2-resident) with 1-step prefetch.
// ---------------------------------------------------------------------------
__global__ __launch_bounds__(256)
void lstm_rec(const int* __restrict__ x,
              const float* __restrict__ Whh_f,
              const float* __restrict__ Whh_b)
{
    const int j   = threadIdx.x;
    const int bg  = blockIdx.x;   // batch group: rows bg*4 .. bg*4+3
    const int dir = blockIdx.y;

    const float* __restrict__ W = dir ? Whh_b : Whh_f;

    __shared__ int toks[4][Sz];
    __shared__ __align__(16) float h_sh[4 * Hz];
    __shared__ float gates[4 * Gz];

    for (int p = j; p < 4 * Sz; p += 256) {
        int r = p >> 9, t = p & 511;
        toks[r][t] = x[(bg * 4 + r) * Sz + t];
    }
    h_sh[j] = 0.0f;   // 256 entries, one per thread

    // W_hh row j in registers, packed for f32x2
    ulonglong2 wv[16];
    const ulonglong2* Wp = (const ulonglong2*)(W + j * Hz);
#pragma unroll
    for (int m = 0; m < 16; m++) wv[m] = Wp[m];

    const int r_own = j >> 6;
    const int e_own = j & 63;
    float c = 0.0f, h_own = 0.0f;

    const float* __restrict__ tb = g_table + dir * Gz + j;

    __syncthreads();

    int t = dir ? (Sz - 1) : 0;
    const int dt = dir ? -1 : 1;

    float xc[4];
#pragma unroll
    for (int r = 0; r < 4; r++) xc[r] = tb[(size_t)toks[r][t] * NC];

#pragma unroll 1
    for (int s = 0; s < Sz; s++) {
        int tn = t + dt;
        float xn[4] = {0, 0, 0, 0};
        if (s < Sz - 1) {
#pragma unroll
            for (int r = 0; r < 4; r++) xn[r] = tb[(size_t)toks[r][tn] * NC];
        }

        // gates[r][j] = xc[r] + dot(W_hh[j], h[r])
#pragma unroll
        for (int r = 0; r < 4; r++) {
            unsigned long long a2;
            PACK2(a2, xc[r], 0.0f);
            const ulonglong2* hp = (const ulonglong2*)(h_sh + r * Hz);
#pragma unroll
            for (int m = 0; m < 16; m++) {
                ulonglong2 hv = hp[m];
                FMA2(a2, wv[m].x, hv.x);
                FMA2(a2, wv[m].y, hv.y);
            }
            float lo, hi;
            UNPACK2(lo, hi, a2);
            gates[r * Gz + j] = lo + hi;
        }
        __syncthreads();

        // update owned cell
        {
            const float* g = gates + r_own * Gz;
            float gi = g[e_own];
            float gf = g[Hz + e_own];
            float gg = g[2 * Hz + e_own];
            float go = g[3 * Hz + e_own];
            c = sigmf(gf) * c + sigmf(gi) * tanhp(gg);
            h_own = sigmf(go) * tanhp(c);
            h_sh[r_own * Hz + e_own] = h_own;
        }
        __syncthreads();

#pragma unroll
        for (int r = 0; r < 4; r++) xc[r] = xn[r];
        t = tn;
    }

    g_hfin[(size_t)(dir * Bz + bg * 4 + r_own) * Hz + e_own] = h_own;
}

// ---------------------------------------------------------------------------
// Kernel 3: final FC + sigmoid
// ---------------------------------------------------------------------------
__global__ void final_fc(const float* __restrict__ fcw,
                         const float* __restrict__ fcb,
                         float* __restrict__ out)
{
    int b = threadIdx.x;
    if (b >= Bz) return;
    float acc = fcb[0];
    const float* hf = g_hfin + b * Hz;
    const float* hb = g_hfin + Bz * Hz + b * Hz;
#pragma unroll
    for (int u = 0; u < Hz; u++) {
        acc = fmaf(hf[u], fcw[u], acc);
        acc = fmaf(hb[u], fcw[Hz + u], acc);
    }
    out[b] = __fdividef(1.0f, 1.0f + __expf(-acc));
}

// ---------------------------------------------------------------------------
extern "C" void kernel_launch(void* const* d_in, const int* in_sizes, int n_in,
                              void* d_out, int out_size)
{
    const int*   x     = (const int*)  d_in[0];
    const float* emb   = (const float*)d_in[1];
    const float* Wih_f = (const float*)d_in[2];
    const float* Whh_f = (const float*)d_in[3];
    const float* bih_f = (const float*)d_in[4];
    const float* bhh_f = (const float*)d_in[5];
    const float* Wih_b = (const float*)d_in[6];
    const float* Whh_b = (const float*)d_in[7];
    const float* bih_b = (const float*)d_in[8];
    const float* bhh_b = (const float*)d_in[9];
    const float* fcw   = (const float*)d_in[10];
    const float* fcb   = (const float*)d_in[11];
    float* out = (float*)d_out;

    dim3 g1(VP / 64, NC / 64);   // 782 x 8
    vocab_gemm<<<g1, 256>>>(emb, Wih_f, bih_f, bhh_f, Wih_b, bih_b, bhh_b);

    dim3 g2(Bz / 4, 2);          // 64 x 2 = 128 blocks (one wave)
    lstm_rec<<<g2, 256>>>(x, Whh_f, Whh_b);

    final_fc<<<1, 256>>>(fcw, fcb, out);
}